// round 8
// baseline (speedup 1.0000x reference)
#include <cuda_runtime.h>
#include <cstdint>

#define Bn 2048
#define Tn 512
#define Hn 16
#define Ln 8
#define WPB 7                          // warps per CTA, 1 batch per warp
#define NBLK ((Bn + WPB - 1) / WPB)    // 293 CTAs -> ~2 per SM
#define CHUNK 16
#define NCHUNK (Tn / CHUNK)

typedef unsigned long long ull;
typedef unsigned int u32;

// Ping-pong scratch for inter-layer hidden sequences (64 MB each).
__device__ float g_bufA[(size_t)Bn * Tn * Hn];
__device__ float g_bufB[(size_t)Bn * Tn * Hn];

// ---- packed fp32x2 ops (Blackwell) ----
__device__ __forceinline__ void ffma2(ull& d, ull a, ull b) {
    asm("fma.rn.f32x2 %0, %1, %2, %0;" : "+l"(d) : "l"(a), "l"(b));
}
__device__ __forceinline__ ull fmul2(ull a, ull b) {
    ull r; asm("mul.rn.f32x2 %0, %1, %2;" : "=l"(r) : "l"(a), "l"(b)); return r;
}
__device__ __forceinline__ float2 u2f(ull a) {
    float2 f;
    asm("mov.b64 {%0,%1}, %2;" : "=f"(f.x), "=f"(f.y) : "l"(a));
    return f;
}
__device__ __forceinline__ ull pack2(float x, float y) {
    ull r;
    asm("mov.b64 %0, {%1,%2};" : "=l"(r) : "f"(x), "f"(y));
    return r;
}
// Load 16 contiguous floats as 8 packed f32x2 (4x 128-bit loads).
__device__ __forceinline__ void load8(ull* d, const float* p) {
    const ulonglong2* q = (const ulonglong2*)p;
    ulonglong2 v0 = q[0], v1 = q[1], v2 = q[2], v3 = q[3];
    d[0] = v0.x; d[1] = v0.y; d[2] = v1.x; d[3] = v1.y;
    d[4] = v2.x; d[5] = v2.y; d[6] = v3.x; d[7] = v3.y;
}
__device__ __forceinline__ float tanha(float x) {
    float r; asm("tanh.approx.f32 %0, %1;" : "=f"(r) : "f"(x)); return r;
}
// Predicated global store — single @p STG, no BSSY/BSYNC.
__device__ __forceinline__ void st_pred(float* addr, float v, int pred) {
    asm volatile("{ .reg .pred p; setp.ne.s32 p, %0, 0; @p st.global.f32 [%1], %2; }"
                 :: "r"(pred), "l"(addr), "f"(v));
}
__device__ __forceinline__ void cp16(u32 saddr, const float* g) {
    asm volatile("cp.async.cg.shared.global [%0], [%1], 16;" :: "r"(saddr), "l"(g));
}
__device__ __forceinline__ void cp_commit() { asm volatile("cp.async.commit_group;"); }
__device__ __forceinline__ void cp_wait0()  { asm volatile("cp.async.wait_group 0;"); }

// One LSTM layer. Warp = ONE batch element (2048 warps total, 3.5/SMSP).
// Lanes 0-15 : rows (j, 32+j)    -> gates (i, g)
// Lanes 16-31: rows (16+j, 48+j) -> gates (f, o)
// Sigmoid rows have 0.5 pre-folded into weights/bias (per-lane), so
// sigmoid(raw) = 0.5*tanh(acc)+0.5 with acc already halved.
// x staged via cp.async chunks; x-projection pipelined one step ahead.
template <bool WRITE_ALL>
__global__ void __launch_bounds__(224, 2)
lstm_layer(const float* __restrict__ in, float* __restrict__ out,
           const float* __restrict__ Wih, const float* __restrict__ Whh,
           const float* __restrict__ bih, const float* __restrict__ bhh)
{
    __shared__ __align__(16) float sh[WPB][2][32];            // [warp][parity][lane] (0-15 scratch, 16-31 = h)
    __shared__ __align__(16) float xs[WPB][2][CHUNK][Hn];     // [warp][buf][step][j]

    const int warp = threadIdx.x >> 5;
    const int lane = threadIdx.x & 31;
    const int b = blockIdx.x * WPB + warp;
    if (b >= Bn) return;   // warp-uniform exit

    const int j   = lane & 15;
    const bool lo = lane < 16;
    const int r0  = lane;        // i | f rows (both sigmoid)
    const int r1  = lane + 32;   // g | o rows (tanh | sigmoid)

    // ---- weights -> registers; fold 0.5 into sigmoid rows ----
    ull wx0[8], wh0[8], wx1[8], wh1[8];
    load8(wx0, Wih + r0 * Hn);  load8(wh0, Whh + r0 * Hn);
    load8(wx1, Wih + r1 * Hn);  load8(wh1, Whh + r1 * Hn);
    const ull halfpack = pack2(0.5f, 0.5f);
#pragma unroll
    for (int i = 0; i < 8; i++) {          // r0 is always sigmoid
        wx0[i] = fmul2(wx0[i], halfpack);
        wh0[i] = fmul2(wh0[i], halfpack);
    }
    if (!lo) {                             // r1 = o gate (sigmoid) on hi lanes
#pragma unroll
        for (int i = 0; i < 8; i++) {
            wx1[i] = fmul2(wx1[i], halfpack);
            wh1[i] = fmul2(wh1[i], halfpack);
        }
    }
    const ull bias0 = pack2(0.5f * (bih[r0] + bhh[r0]), 0.0f);
    const ull bias1 = pack2((lo ? 1.0f : 0.5f) * (bih[r1] + bhh[r1]), 0.0f);

    // pass-B constants: lo = tanh(g), hi = sigmoid(o) (acc pre-halved)
    const float pB = lo ? 1.0f : 0.5f;
    const float qB = lo ? 0.0f : 0.5f;

    sh[warp][0][lane] = 0.0f;
    float c = 0.0f;

    const float* xptr = in + (size_t)b * Tn * Hn;
    float*       orow = out + (size_t)b * Tn * Hn;

    // prefetch chunk 0 into buffer 0 (1 KB/warp = 2 cp16 per lane)
    {
        u32 s0 = (u32)__cvta_generic_to_shared(&xs[warp][0][0][0]);
        cp16(s0 + lane * 16,        xptr + lane * 4);
        cp16(s0 + (lane + 32) * 16, xptr + (lane + 32) * 4);
        cp_commit();
    }
    __syncwarp();

    ull ax0, ax1;   // pipelined x-projection accumulators

    for (int ch = 0; ch < NCHUNK; ch++) {
        const int cur = ch & 1;
        cp_wait0();
        __syncwarp();

        // prefetch chunk ch+1 (clamped refetch at tail — harmless)
        {
            const int nch = (ch + 1 < NCHUNK) ? ch + 1 : ch;
            const float* g = xptr + nch * (CHUNK * Hn);
            u32 s0 = (u32)__cvta_generic_to_shared(&xs[warp][cur ^ 1][0][0]);
            cp16(s0 + lane * 16,        g + lane * 4);
            cp16(s0 + (lane + 32) * 16, g + (lane + 32) * 4);
            cp_commit();
        }

        // prologue: x-projection for s = 0 of this chunk
        {
            ull xv[8];
            load8(xv, &xs[warp][cur][0][0]);
            ax0 = bias0; ax1 = bias1;
#pragma unroll
            for (int i = 0; i < 8; i++) { ffma2(ax0, wx0[i], xv[i]); ffma2(ax1, wx1[i], xv[i]); }
        }

#pragma unroll 4
        for (int s = 0; s < CHUNK; s++) {
            const int t = ch * CHUNK + s;

            // --- critical: h-projection onto pipelined x-projection ---
            ull hp[8];
            load8(hp, &sh[warp][s & 1][16]);
            ull a0 = ax0, a1 = ax1;
#pragma unroll
            for (int i = 0; i < 8; i++) { ffma2(a0, wh0[i], hp[i]); ffma2(a1, wh1[i], hp[i]); }

            // --- off-chain: x-projection for step s+1 (fills latency shadow) ---
            {
                ull xv[8];
                load8(xv, &xs[warp][cur][(s + 1) & 15][0]);  // s=15: dummy, redone next chunk
                ax0 = bias0; ax1 = bias1;
#pragma unroll
                for (int i = 0; i < 8; i++) { ffma2(ax0, wx0[i], xv[i]); ffma2(ax1, wx1[i], xv[i]); }
            }

            // --- activations ---
            float2 A0 = u2f(a0), A1 = u2f(a1);
            const float vA = A0.x + A0.y;   // gate i | f (pre-halved)
            const float vB = A1.x + A1.y;   // gate g | o (g raw, o pre-halved)

            const float tA = fmaf(0.5f, tanha(vA), 0.5f);   // sig(i) | sig(f)
            const float tB = fmaf(pB, tanha(vB), qB);       // tanh(g) | sig(o)

            // lo sends sig(i)*tanh(g); hi sends sig(f) (unused by lo)
            const float v   = lo ? (tA * tB) : tA;
            const float x16 = __shfl_xor_sync(0xffffffffu, v, 16);

            c = fmaf(tA, c, x16);           // valid on hi lanes only
            const float h = tB * tanha(c);

            sh[warp][(s + 1) & 1][lane] = h;   // lo half = scratch, hi half = h
            __syncwarp();
            if (WRITE_ALL || t == Tn - 1)
                st_pred(orow + t * Hn + j, h, !lo);
        }
    }
}

// Readout: position = last @ Wp^T + bp ; orientation = tanh(last @ Wo^T + bo)
__global__ void head_kernel(const float* __restrict__ hbuf,
                            const float* __restrict__ Wp, const float* __restrict__ bp,
                            const float* __restrict__ Wo, const float* __restrict__ bo,
                            float* __restrict__ out)
{
    int b = blockIdx.x * blockDim.x + threadIdx.x;
    if (b >= Bn) return;
    const float* h = hbuf + (size_t)b * Tn * Hn + (size_t)(Tn - 1) * Hn;
    float hv[16];
#pragma unroll
    for (int i = 0; i < 16; i++) hv[i] = h[i];

#pragma unroll
    for (int r = 0; r < 3; r++) {
        float s = bp[r];
#pragma unroll
        for (int k = 0; k < 16; k++) s += hv[k] * Wp[r * 16 + k];
        out[b * 6 + r] = s;
    }
#pragma unroll
    for (int r = 0; r < 3; r++) {
        float s = bo[r];
#pragma unroll
        for (int k = 0; k < 16; k++) s += hv[k] * Wo[r * 16 + k];
        out[b * 6 + 3 + r] = tanha(s);
    }
}

extern "C" void kernel_launch(void* const* d_in, const int* in_sizes, int n_in,
                              void* d_out, int out_size)
{
    const float* x   = (const float*)d_in[0];
    const float* Wih = (const float*)d_in[1];
    const float* Whh = (const float*)d_in[2];
    const float* bih = (const float*)d_in[3];
    const float* bhh = (const float*)d_in[4];
    const float* Wp  = (const float*)d_in[5];
    const float* bp  = (const float*)d_in[6];
    const float* Wo  = (const float*)d_in[7];
    const float* bo  = (const float*)d_in[8];
    float* out = (float*)d_out;

    float *bufA, *bufB;
    cudaGetSymbolAddress((void**)&bufA, g_bufA);
    cudaGetSymbolAddress((void**)&bufB, g_bufB);

    const float* cur = x;
    for (int l = 0; l < Ln; l++) {
        float* o = (l & 1) ? bufB : bufA;
        if (l != Ln - 1)
            lstm_layer<true><<<NBLK, 224>>>(cur, o,
                                            Wih + (size_t)l * 64 * Hn,
                                            Whh + (size_t)l * 64 * Hn,
                                            bih + (size_t)l * 64,
                                            bhh + (size_t)l * 64);
        else
            lstm_layer<false><<<NBLK, 224>>>(cur, o,
                                             Wih + (size_t)l * 64 * Hn,
                                             Whh + (size_t)l * 64 * Hn,
                                             bih + (size_t)l * 64,
                                             bhh + (size_t)l * 64);
        cur = o;
    }
    head_kernel<<<(Bn + 255) / 256, 256>>>(cur, Wp, bp, Wo, bo, out);
}